// round 13
// baseline (speedup 1.0000x reference)
#include <cuda_runtime.h>
#include <cuda_fp16.h>
#include <math.h>
#include <stdint.h>

// Problem constants
#define T_TOK 2048
#define D_MOD 1024
#define N_EXP 8
#define H_HID 2048
#define TOPK  2
#define NA    (T_TOK*TOPK)   // 4096 assignments

// GEMM tiling
#define BM 128
#define BN 128
#define BK 16

// -------- device scratch (no cudaMalloc allowed) --------
__device__ int    g_count[N_EXP];
__device__ int    g_offset[N_EXP+1];
__device__ int    g_cursor[N_EXP];
__device__ int    g_tok_e[NA];
__device__ float  g_tok_w[NA];
__device__ int    g_assign_tok[NA];
__device__ float  g_assign_w[NA];
__device__ int    g_tok_slot[NA];                                  // token -> its 2 slots
__device__ __align__(16) __half g_Hbuf[(size_t)NA * H_HID];        // 16 MB hidden (fp16)
__device__ __align__(16) float  g_Ybuf[(size_t)NA * D_MOD];        // 16 MB per-assignment outputs

// -------- init: counters only (combine fully overwrites out) --------
__global__ void init_kernel() {
    if (threadIdx.x < N_EXP) {
        g_count[threadIdx.x]  = 0;
        g_cursor[threadIdx.x] = 0;
    }
}

// -------- gate: logits, top-2, softmax --------
__global__ void gate_kernel(const float* __restrict__ X,
                            const float* __restrict__ Wg,
                            const float* __restrict__ bg,
                            float* __restrict__ out_idx) {
    int warp = (blockIdx.x * blockDim.x + threadIdx.x) >> 5;
    int lane = threadIdx.x & 31;
    if (warp >= T_TOK) return;
    const float* xr = X + (size_t)warp * D_MOD;

    float acc[N_EXP];
#pragma unroll
    for (int e = 0; e < N_EXP; e++) acc[e] = 0.f;

    for (int i = lane; i < D_MOD; i += 32) {
        float xv = xr[i];
        const float* wr = Wg + (size_t)i * N_EXP;
#pragma unroll
        for (int e = 0; e < N_EXP; e++) acc[e] += xv * wr[e];
    }
#pragma unroll
    for (int e = 0; e < N_EXP; e++) {
#pragma unroll
        for (int o = 16; o > 0; o >>= 1)
            acc[e] += __shfl_xor_sync(0xFFFFFFFFu, acc[e], o);
    }

    if (lane == 0) {
        float l[N_EXP];
#pragma unroll
        for (int e = 0; e < N_EXP; e++) l[e] = acc[e] + bg[e];

        float v0 = -1e30f, v1 = -1e30f;
        int   i0 = 0,      i1 = 0;
#pragma unroll
        for (int e = 0; e < N_EXP; e++) {
            if (l[e] > v0)      { v1 = v0; i1 = i0; v0 = l[e]; i0 = e; }
            else if (l[e] > v1) { v1 = l[e]; i1 = e; }
        }
        float s  = expf(v1 - v0);
        float w0 = 1.f / (1.f + s);
        float w1 = s * w0;

        int t = warp;
        g_tok_e[t*2+0] = i0;  g_tok_w[t*2+0] = w0;
        g_tok_e[t*2+1] = i1;  g_tok_w[t*2+1] = w1;
        atomicAdd(&g_count[i0], 1);
        atomicAdd(&g_count[i1], 1);
        if (out_idx) {
            out_idx[t*2+0] = (float)i0;
            out_idx[t*2+1] = (float)i1;
        }
    }
}

__global__ void offsets_kernel() {
    if (threadIdx.x == 0 && blockIdx.x == 0) {
        int run = 0;
        g_offset[0] = 0;
#pragma unroll
        for (int e = 0; e < N_EXP; e++) { run += g_count[e]; g_offset[e+1] = run; }
    }
}

__global__ void scatter_kernel() {
    int t = blockIdx.x * blockDim.x + threadIdx.x;
    if (t >= T_TOK) return;
#pragma unroll
    for (int j = 0; j < TOPK; j++) {
        int e = g_tok_e[t*2+j];
        int pos = atomicAdd(&g_cursor[e], 1);
        int slot = g_offset[e] + pos;
        g_assign_tok[slot] = t;
        g_assign_w[slot]   = g_tok_w[t*2+j];
        g_tok_slot[t*2+j]  = slot;
    }
}

// -------- fp16 helpers --------
__device__ __forceinline__ uint32_t packh(float lo, float hi) {
    __half2 h = __floats2half2_rn(lo, hi);
    return *reinterpret_cast<uint32_t*>(&h);
}
__device__ __forceinline__ void mma16(float* d, const uint32_t* a, const uint32_t* b) {
    asm volatile(
        "mma.sync.aligned.m16n8k16.row.col.f32.f16.f16.f32 "
        "{%0,%1,%2,%3},{%4,%5,%6,%7},{%8,%9},{%0,%1,%2,%3};\n"
        : "+f"(d[0]), "+f"(d[1]), "+f"(d[2]), "+f"(d[3])
        : "r"(a[0]), "r"(a[1]), "r"(a[2]), "r"(a[3]), "r"(b[0]), "r"(b[1]));
}

// smem strides (uint32 units; each uint32 = packed k-pair of halves)
#define ASTR 12    // A: As[row][kpair], 8 kpairs + pad -> fragment reads conflict-free
#define BSTR 136   // B: Bs[kpair][n], 128 n + pad    -> conflict-free both ways

// ============ FFN1: H = gelu(Xg @ W1[e] + b1[e]) (fp16 tensor cores) ============
__global__ __launch_bounds__(256)
void gemm1_kernel(const float* __restrict__ X,
                  const float* __restrict__ W1,
                  const float* __restrict__ b1) {
    __shared__ uint32_t As[2][BM][ASTR];
    __shared__ uint32_t Bs[2][BK/2][BSTR];
    __shared__ int s_tok[BM];

    int e    = blockIdx.z;
    int base = g_offset[e];
    int cnt  = g_offset[e+1] - base;
    int m0   = blockIdx.y * BM;
    if (m0 >= cnt) return;
    int n0   = blockIdx.x * BN;
    int tid  = threadIdx.x;

    if (tid < BM) {
        int r = m0 + tid;
        s_tok[tid] = g_assign_tok[base + ((r < cnt) ? r : 0)];
    }
    __syncthreads();

    int lane = tid & 31, warp = tid >> 5;
    int wm = warp & 3, wn = warp >> 2;

    // A loader: row = tid>>1 (0..127), kh = (tid&1)*8 (k offset in floats)
    int arow = tid >> 1;
    int akh  = (tid & 1) * 8;
    const float* pA = X + (size_t)s_tok[arow] * D_MOD + akh;
    // B loader: kp = tid>>5 (0..7 -> k rows 2kp,2kp+1), n4 = (lane)*4
    int bkp = tid >> 5;
    int bn4 = (tid & 31) * 4;
    const float* pB = W1 + (size_t)e * D_MOD * H_HID + n0 + bn4;

    float4 ra0, ra1, rb0, rb1;
    ra0 = *(const float4*)(pA);
    ra1 = *(const float4*)(pA + 4);
    rb0 = *(const float4*)(pB + (size_t)(2*bkp)     * H_HID);
    rb1 = *(const float4*)(pB + (size_t)(2*bkp + 1) * H_HID);

    {
        uint32_t* as = &As[0][arow][akh >> 1];
        as[0] = packh(ra0.x, ra0.y); as[1] = packh(ra0.z, ra0.w);
        as[2] = packh(ra1.x, ra1.y); as[3] = packh(ra1.z, ra1.w);
        uint32_t* bs = &Bs[0][bkp][bn4];
        bs[0] = packh(rb0.x, rb1.x); bs[1] = packh(rb0.y, rb1.y);
        bs[2] = packh(rb0.z, rb1.z); bs[3] = packh(rb0.w, rb1.w);
    }
    __syncthreads();

    float acc[2][8][4];
#pragma unroll
    for (int mt = 0; mt < 2; mt++)
#pragma unroll
        for (int nt = 0; nt < 8; nt++)
#pragma unroll
            for (int j = 0; j < 4; j++) acc[mt][nt][j] = 0.f;

    const int nit = D_MOD / BK; // 64
    int buf = 0;
    for (int it = 0; it < nit; ++it) {
        int k0n = (it + 1) * BK;
        if (it + 1 < nit) {
            ra0 = *(const float4*)(pA + k0n);
            ra1 = *(const float4*)(pA + k0n + 4);
            rb0 = *(const float4*)(pB + (size_t)(k0n + 2*bkp)     * H_HID);
            rb1 = *(const float4*)(pB + (size_t)(k0n + 2*bkp + 1) * H_HID);
        }
        {
            uint32_t afr[2][4], bfr[8][2];
            int c = lane & 3;
#pragma unroll
            for (int mt = 0; mt < 2; ++mt) {
                int r = wm * 32 + mt * 16 + (lane >> 2);
                afr[mt][0] = As[buf][r][c];
                afr[mt][1] = As[buf][r + 8][c];
                afr[mt][2] = As[buf][r][c + 4];
                afr[mt][3] = As[buf][r + 8][c + 4];
            }
#pragma unroll
            for (int nt = 0; nt < 8; ++nt) {
                int n = wn * 64 + nt * 8 + (lane >> 2);
                bfr[nt][0] = Bs[buf][c][n];
                bfr[nt][1] = Bs[buf][c + 4][n];
            }
#pragma unroll
            for (int mt = 0; mt < 2; ++mt)
#pragma unroll
                for (int nt = 0; nt < 8; ++nt)
                    mma16(acc[mt][nt], afr[mt], bfr[nt]);
        }
        if (it + 1 < nit) {
            buf ^= 1;
            uint32_t* as = &As[buf][arow][akh >> 1];
            as[0] = packh(ra0.x, ra0.y); as[1] = packh(ra0.z, ra0.w);
            as[2] = packh(ra1.x, ra1.y); as[3] = packh(ra1.z, ra1.w);
            uint32_t* bs = &Bs[buf][bkp][bn4];
            bs[0] = packh(rb0.x, rb1.x); bs[1] = packh(rb0.y, rb1.y);
            bs[2] = packh(rb0.z, rb1.z); bs[3] = packh(rb0.w, rb1.w);
        }
        __syncthreads();
    }

    // epilogue: bias + gelu(tanh) -> Hbuf (fp16)
#pragma unroll
    for (int mt = 0; mt < 2; ++mt) {
        int rt0 = wm * 32 + mt * 16 + (lane >> 2);
#pragma unroll
        for (int half = 0; half < 2; ++half) {
            int r = m0 + rt0 + half * 8;
            if (r < cnt) {
                __half* Hrow = g_Hbuf + (size_t)(base + r) * H_HID + n0 + wn * 64;
                const float* brow = b1 + e * H_HID + n0 + wn * 64;
#pragma unroll
                for (int nt = 0; nt < 8; ++nt) {
                    int cc = nt * 8 + (lane & 3) * 2;
                    float v0 = acc[mt][nt][half * 2 + 0] + brow[cc];
                    float v1 = acc[mt][nt][half * 2 + 1] + brow[cc + 1];
                    float u0 = 0.7978845608028654f * (v0 + 0.044715f * v0 * v0 * v0);
                    float u1 = 0.7978845608028654f * (v1 + 0.044715f * v1 * v1 * v1);
                    float g0 = 0.5f * v0 * (1.f + tanhf(u0));
                    float g1 = 0.5f * v1 * (1.f + tanhf(u1));
                    *(__half2*)(Hrow + cc) = __floats2half2_rn(g0, g1);
                }
            }
        }
    }
}

// ============ FFN2: Ybuf[slot] = w * (H @ W2[e] + b2[e]) (fp16 tensor cores) ============
__global__ __launch_bounds__(256)
void gemm2_kernel(const float* __restrict__ W2,
                  const float* __restrict__ b2) {
    __shared__ uint32_t As[2][BM][ASTR];
    __shared__ uint32_t Bs[2][BK/2][BSTR];
    __shared__ float s_w[BM];

    int e    = blockIdx.z;
    int base = g_offset[e];
    int cnt  = g_offset[e+1] - base;
    int m0   = blockIdx.y * BM;
    if (m0 >= cnt) return;
    int n0   = blockIdx.x * BN;
    int tid  = threadIdx.x;

    if (tid < BM) {
        int r = m0 + tid;
        s_w[tid] = (r < cnt) ? g_assign_w[base + r] : 0.f;
    }
    __syncthreads();

    int lane = tid & 31, warp = tid >> 5;
    int wm = warp & 3, wn = warp >> 2;

    // A loader: Hbuf already fp16 & k-pair packed -> raw uint4 copy
    int arow = tid >> 1;
    int akh  = (tid & 1) * 8;     // k offset in halves
    int sr = m0 + arow; if (sr >= cnt) sr = cnt - 1;   // clamp (stores guarded)
    const __half* pA = g_Hbuf + (size_t)(base + sr) * H_HID + akh;
    int bkp = tid >> 5;
    int bn4 = (tid & 31) * 4;
    const float* pB = W2 + (size_t)e * H_HID * D_MOD + n0 + bn4;

    uint4  ha;
    float4 rb0, rb1;
    ha  = *(const uint4*)(pA);
    rb0 = *(const float4*)(pB + (size_t)(2*bkp)     * D_MOD);
    rb1 = *(const float4*)(pB + (size_t)(2*bkp + 1) * D_MOD);

    {
        *(uint4*)&As[0][arow][akh >> 1] = ha;
        uint32_t* bs = &Bs[0][bkp][bn4];
        bs[0] = packh(rb0.x, rb1.x); bs[1] = packh(rb0.y, rb1.y);
        bs[2] = packh(rb0.z, rb1.z); bs[3] = packh(rb0.w, rb1.w);
    }
    __syncthreads();

    float acc[2][8][4];
#pragma unroll
    for (int mt = 0; mt < 2; mt++)
#pragma unroll
        for (int nt = 0; nt < 8; nt++)
#pragma unroll
            for (int j = 0; j < 4; j++) acc[mt][nt][j] = 0.f;

    const int nit = H_HID / BK; // 128
    int buf = 0;
    for (int it = 0; it < nit; ++it) {
        int k0n = (it + 1) * BK;
        if (it + 1 < nit) {
            ha  = *(const uint4*)(pA + k0n);
            rb0 = *(const float4*)(pB + (size_t)(k0n + 2*bkp)     * D_MOD);
            rb1 = *(const float4*)(pB + (size_t)(k0n + 2*bkp + 1) * D_MOD);
        }
        {
            uint32_t afr[2][4], bfr[8][2];
            int c = lane & 3;
#pragma unroll
            for (int mt = 0; mt < 2; ++mt) {
                int r = wm * 32 + mt * 16 + (lane >> 2);
                afr[mt][0] = As[buf][r][c];
                afr[mt][1] = As[buf][r + 8][c];
                afr[mt][2] = As[buf][r][c + 4];
                afr[mt][3] = As[buf][r + 8][c + 4];
            }
#pragma unroll
            for (int nt = 0; nt < 8; ++nt) {
                int n = wn * 64 + nt * 8 + (lane >> 2);
                bfr[nt][0] = Bs[buf][c][n];
                bfr[nt][1] = Bs[buf][c + 4][n];
            }
#pragma unroll
            for (int mt = 0; mt < 2; ++mt)
#pragma unroll
                for (int nt = 0; nt < 8; ++nt)
                    mma16(acc[mt][nt], afr[mt], bfr[nt]);
        }
        if (it + 1 < nit) {
            buf ^= 1;
            *(uint4*)&As[buf][arow][akh >> 1] = ha;
            uint32_t* bs = &Bs[buf][bkp][bn4];
            bs[0] = packh(rb0.x, rb1.x); bs[1] = packh(rb0.y, rb1.y);
            bs[2] = packh(rb0.z, rb1.z); bs[3] = packh(rb0.w, rb1.w);
        }
        __syncthreads();
    }

    // epilogue: bias + gate-weight scale -> per-assignment buffer (plain stores)
#pragma unroll
    for (int mt = 0; mt < 2; ++mt) {
        int rt0 = wm * 32 + mt * 16 + (lane >> 2);
#pragma unroll
        for (int half = 0; half < 2; ++half) {
            int rtile = rt0 + half * 8;
            int r = m0 + rtile;
            if (r < cnt) {
                float w = s_w[rtile];
                float* yrow = g_Ybuf + (size_t)(base + r) * D_MOD + n0 + wn * 64;
                const float* brow = b2 + e * D_MOD + n0 + wn * 64;
#pragma unroll
                for (int nt = 0; nt < 8; ++nt) {
                    int cc = nt * 8 + (lane & 3) * 2;
                    float y0 = acc[mt][nt][half * 2 + 0] + brow[cc];
                    float y1 = acc[mt][nt][half * 2 + 1] + brow[cc + 1];
                    *(float2*)(yrow + cc) = make_float2(w * y0, w * y1);
                }
            }
        }
    }
}

// -------- combine: out[t] = Ybuf[slot0(t)] + Ybuf[slot1(t)] --------
__global__ void combine_kernel(float* __restrict__ out) {
    int t  = blockIdx.x;
    int s0 = g_tok_slot[t*2+0];
    int s1 = g_tok_slot[t*2+1];
    const float4* y0 = (const float4*)(g_Ybuf + (size_t)s0 * D_MOD);
    const float4* y1 = (const float4*)(g_Ybuf + (size_t)s1 * D_MOD);
    float4* o = (float4*)(out + (size_t)t * D_MOD);
    for (int i = threadIdx.x; i < D_MOD/4; i += blockDim.x) {
        float4 a = y0[i], b = y1[i];
        o[i] = make_float4(a.x + b.x, a.y + b.y, a.z + b.z, a.w + b.w);
    }
}

// -------- launch --------
extern "C" void kernel_launch(void* const* d_in, const int* in_sizes, int n_in,
                              void* d_out, int out_size) {
    const float* X  = (const float*)d_in[0];
    const float* Wg = (const float*)d_in[1];
    const float* bg = (const float*)d_in[2];
    const float* W1 = (const float*)d_in[3];
    const float* b1 = (const float*)d_in[4];
    const float* W2 = (const float*)d_in[5];
    const float* b2 = (const float*)d_in[6];
    (void)in_sizes; (void)n_in;

    float* out = (float*)d_out;
    float* out_idx = (out_size >= T_TOK*D_MOD + TOPK*T_TOK) ? out + T_TOK*D_MOD
                                                            : nullptr;

    init_kernel<<<1, 32>>>();
    gate_kernel<<<T_TOK/8, 256>>>(X, Wg, bg, out_idx);
    offsets_kernel<<<1, 32>>>();
    scatter_kernel<<<T_TOK/256, 256>>>();

    dim3 g1(H_HID/BN, T_TOK/BM, N_EXP);   // 16 x 16 x 8
    gemm1_kernel<<<g1, 256>>>(X, W1, b1);
    dim3 g2(D_MOD/BN, T_TOK/BM, N_EXP);   // 8 x 16 x 8
    gemm2_kernel<<<g2, 256>>>(W2, b2);
    combine_kernel<<<T_TOK, 256>>>(out);
}

// round 16
// speedup vs baseline: 1.0273x; 1.0273x over previous
#include <cuda_runtime.h>
#include <cuda_fp16.h>
#include <math.h>
#include <stdint.h>

// Problem constants
#define T_TOK 2048
#define D_MOD 1024
#define N_EXP 8
#define H_HID 2048
#define TOPK  2
#define NA    (T_TOK*TOPK)   // 4096 assignments

// GEMM tiling
#define BM 128
#define BN 128
#define BK 16

// -------- device scratch (no cudaMalloc allowed) --------
__device__ int    g_count[N_EXP];
__device__ int    g_offset[N_EXP+1];
__device__ int    g_cursor[N_EXP];
__device__ int    g_tok_e[NA];
__device__ float  g_tok_w[NA];
__device__ int    g_assign_tok[NA];
__device__ float  g_assign_w[NA];
__device__ int    g_tok_slot[NA];                                  // token -> its 2 slots
__device__ __align__(16) __half g_Xh [(size_t)T_TOK * D_MOD];      //  4 MB X in fp16
__device__ __align__(16) __half g_Hbuf[(size_t)NA * H_HID];        // 16 MB hidden (fp16)
__device__ __align__(16) float  g_Ybuf[(size_t)NA * D_MOD];        // 16 MB per-assignment outputs

// -------- init: counters only (combine fully overwrites out) --------
__global__ void init_kernel() {
    if (threadIdx.x < N_EXP) {
        g_count[threadIdx.x]  = 0;
        g_cursor[threadIdx.x] = 0;
    }
}

// -------- gate: logits, top-2, softmax; also writes X in fp16 --------
__global__ void gate_kernel(const float* __restrict__ X,
                            const float* __restrict__ Wg,
                            const float* __restrict__ bg,
                            float* __restrict__ out_idx) {
    int warp = (blockIdx.x * blockDim.x + threadIdx.x) >> 5;
    int lane = threadIdx.x & 31;
    if (warp >= T_TOK) return;
    const float* xr = X + (size_t)warp * D_MOD;
    __half*      xh = g_Xh + (size_t)warp * D_MOD;

    float acc[N_EXP];
#pragma unroll
    for (int e = 0; e < N_EXP; e++) acc[e] = 0.f;

    for (int i = lane; i < D_MOD; i += 32) {
        float xv = xr[i];
        xh[i] = __float2half_rn(xv);          // fp16 copy for gemm1 A-path
        const float* wr = Wg + (size_t)i * N_EXP;
#pragma unroll
        for (int e = 0; e < N_EXP; e++) acc[e] += xv * wr[e];
    }
#pragma unroll
    for (int e = 0; e < N_EXP; e++) {
#pragma unroll
        for (int o = 16; o > 0; o >>= 1)
            acc[e] += __shfl_xor_sync(0xFFFFFFFFu, acc[e], o);
    }

    if (lane == 0) {
        float l[N_EXP];
#pragma unroll
        for (int e = 0; e < N_EXP; e++) l[e] = acc[e] + bg[e];

        float v0 = -1e30f, v1 = -1e30f;
        int   i0 = 0,      i1 = 0;
#pragma unroll
        for (int e = 0; e < N_EXP; e++) {
            if (l[e] > v0)      { v1 = v0; i1 = i0; v0 = l[e]; i0 = e; }
            else if (l[e] > v1) { v1 = l[e]; i1 = e; }
        }
        float s  = expf(v1 - v0);
        float w0 = 1.f / (1.f + s);
        float w1 = s * w0;

        int t = warp;
        g_tok_e[t*2+0] = i0;  g_tok_w[t*2+0] = w0;
        g_tok_e[t*2+1] = i1;  g_tok_w[t*2+1] = w1;
        atomicAdd(&g_count[i0], 1);
        atomicAdd(&g_count[i1], 1);
        if (out_idx) {
            out_idx[t*2+0] = (float)i0;
            out_idx[t*2+1] = (float)i1;
        }
    }
}

// -------- offsets + scatter fused (single block, 1024 threads) --------
__global__ void scatter_kernel() {
    int tid = threadIdx.x;
    if (tid == 0) {
        int run = 0;
        g_offset[0] = 0;
#pragma unroll
        for (int e = 0; e < N_EXP; e++) { run += g_count[e]; g_offset[e+1] = run; }
    }
    __syncthreads();
#pragma unroll
    for (int rep = 0; rep < 2; rep++) {
        int t = tid + rep * 1024;
#pragma unroll
        for (int j = 0; j < TOPK; j++) {
            int e = g_tok_e[t*2+j];
            int pos = atomicAdd(&g_cursor[e], 1);
            int slot = g_offset[e] + pos;
            g_assign_tok[slot] = t;
            g_assign_w[slot]   = g_tok_w[t*2+j];
            g_tok_slot[t*2+j]  = slot;
        }
    }
}

// -------- fp16 helpers --------
__device__ __forceinline__ uint32_t packh(float lo, float hi) {
    __half2 h = __floats2half2_rn(lo, hi);
    return *reinterpret_cast<uint32_t*>(&h);
}
__device__ __forceinline__ void mma16(float* d, const uint32_t* a, const uint32_t* b) {
    asm volatile(
        "mma.sync.aligned.m16n8k16.row.col.f32.f16.f16.f32 "
        "{%0,%1,%2,%3},{%4,%5,%6,%7},{%8,%9},{%0,%1,%2,%3};\n"
        : "+f"(d[0]), "+f"(d[1]), "+f"(d[2]), "+f"(d[3])
        : "r"(a[0]), "r"(a[1]), "r"(a[2]), "r"(a[3]), "r"(b[0]), "r"(b[1]));
}

// smem strides (uint32 units; each uint32 = packed k-pair of halves)
#define ASTR 12    // A: As[row][kpair], 8 kpairs + pad -> fragment reads conflict-free
#define BSTR 136   // B: Bs[kpair][n], 128 n + pad    -> conflict-free both ways

// ============ FFN1: H = gelu(Xh_g @ W1[e] + b1[e]) (fp16 tensor cores) ============
__global__ __launch_bounds__(256)
void gemm1_kernel(const float* __restrict__ W1,
                  const float* __restrict__ b1) {
    __shared__ uint32_t As[2][BM][ASTR];
    __shared__ uint32_t Bs[2][BK/2][BSTR];
    __shared__ int s_tok[BM];

    int e    = blockIdx.z;
    int base = g_offset[e];
    int cnt  = g_offset[e+1] - base;
    int m0   = blockIdx.y * BM;
    if (m0 >= cnt) return;
    int n0   = blockIdx.x * BN;
    int tid  = threadIdx.x;

    if (tid < BM) {
        int r = m0 + tid;
        s_tok[tid] = g_assign_tok[base + ((r < cnt) ? r : 0)];
    }
    __syncthreads();

    int lane = tid & 31, warp = tid >> 5;
    int wm = warp & 3, wn = warp >> 2;

    // A loader: raw uint4 from fp16 X (pair-packed naturally) — proven gemm2 pattern
    int arow = tid >> 1;
    int akh  = (tid & 1) * 8;     // k offset in halves
    const __half* pA = g_Xh + (size_t)s_tok[arow] * D_MOD + akh;
    // B loader: kp = tid>>5 (0..7 -> k rows 2kp,2kp+1), n4 = (lane)*4
    int bkp = tid >> 5;
    int bn4 = (tid & 31) * 4;
    const float* pB = W1 + (size_t)e * D_MOD * H_HID + n0 + bn4;

    uint4  ha;
    float4 rb0, rb1;
    ha  = *(const uint4*)(pA);
    rb0 = *(const float4*)(pB + (size_t)(2*bkp)     * H_HID);
    rb1 = *(const float4*)(pB + (size_t)(2*bkp + 1) * H_HID);

    {
        *(uint4*)&As[0][arow][akh >> 1] = ha;
        uint32_t* bs = &Bs[0][bkp][bn4];
        bs[0] = packh(rb0.x, rb1.x); bs[1] = packh(rb0.y, rb1.y);
        bs[2] = packh(rb0.z, rb1.z); bs[3] = packh(rb0.w, rb1.w);
    }
    __syncthreads();

    float acc[2][8][4];
#pragma unroll
    for (int mt = 0; mt < 2; mt++)
#pragma unroll
        for (int nt = 0; nt < 8; nt++)
#pragma unroll
            for (int j = 0; j < 4; j++) acc[mt][nt][j] = 0.f;

    const int nit = D_MOD / BK; // 64
    int buf = 0;
    for (int it = 0; it < nit; ++it) {
        int k0n = (it + 1) * BK;
        if (it + 1 < nit) {
            ha  = *(const uint4*)(pA + k0n);
            rb0 = *(const float4*)(pB + (size_t)(k0n + 2*bkp)     * H_HID);
            rb1 = *(const float4*)(pB + (size_t)(k0n + 2*bkp + 1) * H_HID);
        }
        {
            uint32_t afr[2][4], bfr[8][2];
            int c = lane & 3;
#pragma unroll
            for (int mt = 0; mt < 2; ++mt) {
                int r = wm * 32 + mt * 16 + (lane >> 2);
                afr[mt][0] = As[buf][r][c];
                afr[mt][1] = As[buf][r + 8][c];
                afr[mt][2] = As[buf][r][c + 4];
                afr[mt][3] = As[buf][r + 8][c + 4];
            }
#pragma unroll
            for (int nt = 0; nt < 8; ++nt) {
                int n = wn * 64 + nt * 8 + (lane >> 2);
                bfr[nt][0] = Bs[buf][c][n];
                bfr[nt][1] = Bs[buf][c + 4][n];
            }
#pragma unroll
            for (int mt = 0; mt < 2; ++mt)
#pragma unroll
                for (int nt = 0; nt < 8; ++nt)
                    mma16(acc[mt][nt], afr[mt], bfr[nt]);
        }
        if (it + 1 < nit) {
            buf ^= 1;
            *(uint4*)&As[buf][arow][akh >> 1] = ha;
            uint32_t* bs = &Bs[buf][bkp][bn4];
            bs[0] = packh(rb0.x, rb1.x); bs[1] = packh(rb0.y, rb1.y);
            bs[2] = packh(rb0.z, rb1.z); bs[3] = packh(rb0.w, rb1.w);
        }
        __syncthreads();
    }

    // epilogue: bias + gelu(tanh) -> Hbuf (fp16)
#pragma unroll
    for (int mt = 0; mt < 2; ++mt) {
        int rt0 = wm * 32 + mt * 16 + (lane >> 2);
#pragma unroll
        for (int half = 0; half < 2; ++half) {
            int r = m0 + rt0 + half * 8;
            if (r < cnt) {
                __half* Hrow = g_Hbuf + (size_t)(base + r) * H_HID + n0 + wn * 64;
                const float* brow = b1 + e * H_HID + n0 + wn * 64;
#pragma unroll
                for (int nt = 0; nt < 8; ++nt) {
                    int cc = nt * 8 + (lane & 3) * 2;
                    float v0 = acc[mt][nt][half * 2 + 0] + brow[cc];
                    float v1 = acc[mt][nt][half * 2 + 1] + brow[cc + 1];
                    float u0 = 0.7978845608028654f * (v0 + 0.044715f * v0 * v0 * v0);
                    float u1 = 0.7978845608028654f * (v1 + 0.044715f * v1 * v1 * v1);
                    float g0 = 0.5f * v0 * (1.f + tanhf(u0));
                    float g1 = 0.5f * v1 * (1.f + tanhf(u1));
                    *(__half2*)(Hrow + cc) = __floats2half2_rn(g0, g1);
                }
            }
        }
    }
}

// ============ FFN2: Ybuf[slot] = w * (H @ W2[e] + b2[e]) (fp16 tensor cores) ============
__global__ __launch_bounds__(256)
void gemm2_kernel(const float* __restrict__ W2,
                  const float* __restrict__ b2) {
    __shared__ uint32_t As[2][BM][ASTR];
    __shared__ uint32_t Bs[2][BK/2][BSTR];
    __shared__ float s_w[BM];

    int e    = blockIdx.z;
    int base = g_offset[e];
    int cnt  = g_offset[e+1] - base;
    int m0   = blockIdx.y * BM;
    if (m0 >= cnt) return;
    int n0   = blockIdx.x * BN;
    int tid  = threadIdx.x;

    if (tid < BM) {
        int r = m0 + tid;
        s_w[tid] = (r < cnt) ? g_assign_w[base + r] : 0.f;
    }
    __syncthreads();

    int lane = tid & 31, warp = tid >> 5;
    int wm = warp & 3, wn = warp >> 2;

    int arow = tid >> 1;
    int akh  = (tid & 1) * 8;     // k offset in halves
    int sr = m0 + arow; if (sr >= cnt) sr = cnt - 1;   // clamp (stores guarded)
    const __half* pA = g_Hbuf + (size_t)(base + sr) * H_HID + akh;
    int bkp = tid >> 5;
    int bn4 = (tid & 31) * 4;
    const float* pB = W2 + (size_t)e * H_HID * D_MOD + n0 + bn4;

    uint4  ha;
    float4 rb0, rb1;
    ha  = *(const uint4*)(pA);
    rb0 = *(const float4*)(pB + (size_t)(2*bkp)     * D_MOD);
    rb1 = *(const float4*)(pB + (size_t)(2*bkp + 1) * D_MOD);

    {
        *(uint4*)&As[0][arow][akh >> 1] = ha;
        uint32_t* bs = &Bs[0][bkp][bn4];
        bs[0] = packh(rb0.x, rb1.x); bs[1] = packh(rb0.y, rb1.y);
        bs[2] = packh(rb0.z, rb1.z); bs[3] = packh(rb0.w, rb1.w);
    }
    __syncthreads();

    float acc[2][8][4];
#pragma unroll
    for (int mt = 0; mt < 2; mt++)
#pragma unroll
        for (int nt = 0; nt < 8; nt++)
#pragma unroll
            for (int j = 0; j < 4; j++) acc[mt][nt][j] = 0.f;

    const int nit = H_HID / BK; // 128
    int buf = 0;
    for (int it = 0; it < nit; ++it) {
        int k0n = (it + 1) * BK;
        if (it + 1 < nit) {
            ha  = *(const uint4*)(pA + k0n);
            rb0 = *(const float4*)(pB + (size_t)(k0n + 2*bkp)     * D_MOD);
            rb1 = *(const float4*)(pB + (size_t)(k0n + 2*bkp + 1) * D_MOD);
        }
        {
            uint32_t afr[2][4], bfr[8][2];
            int c = lane & 3;
#pragma unroll
            for (int mt = 0; mt < 2; ++mt) {
                int r = wm * 32 + mt * 16 + (lane >> 2);
                afr[mt][0] = As[buf][r][c];
                afr[mt][1] = As[buf][r + 8][c];
                afr[mt][2] = As[buf][r][c + 4];
                afr[mt][3] = As[buf][r + 8][c + 4];
            }
#pragma unroll
            for (int nt = 0; nt < 8; ++nt) {
                int n = wn * 64 + nt * 8 + (lane >> 2);
                bfr[nt][0] = Bs[buf][c][n];
                bfr[nt][1] = Bs[buf][c + 4][n];
            }
#pragma unroll
            for (int mt = 0; mt < 2; ++mt)
#pragma unroll
                for (int nt = 0; nt < 8; ++nt)
                    mma16(acc[mt][nt], afr[mt], bfr[nt]);
        }
        if (it + 1 < nit) {
            buf ^= 1;
            *(uint4*)&As[buf][arow][akh >> 1] = ha;
            uint32_t* bs = &Bs[buf][bkp][bn4];
            bs[0] = packh(rb0.x, rb1.x); bs[1] = packh(rb0.y, rb1.y);
            bs[2] = packh(rb0.z, rb1.z); bs[3] = packh(rb0.w, rb1.w);
        }
        __syncthreads();
    }

    // epilogue: bias + gate-weight scale -> per-assignment buffer (plain stores)
#pragma unroll
    for (int mt = 0; mt < 2; ++mt) {
        int rt0 = wm * 32 + mt * 16 + (lane >> 2);
#pragma unroll
        for (int half = 0; half < 2; ++half) {
            int rtile = rt0 + half * 8;
            int r = m0 + rtile;
            if (r < cnt) {
                float w = s_w[rtile];
                float* yrow = g_Ybuf + (size_t)(base + r) * D_MOD + n0 + wn * 64;
                const float* brow = b2 + e * D_MOD + n0 + wn * 64;
#pragma unroll
                for (int nt = 0; nt < 8; ++nt) {
                    int cc = nt * 8 + (lane & 3) * 2;
                    float y0 = acc[mt][nt][half * 2 + 0] + brow[cc];
                    float y1 = acc[mt][nt][half * 2 + 1] + brow[cc + 1];
                    *(float2*)(yrow + cc) = make_float2(w * y0, w * y1);
                }
            }
        }
    }
}

// -------- combine: out[t] = Ybuf[slot0(t)] + Ybuf[slot1(t)] --------
__global__ void combine_kernel(float* __restrict__ out) {
    int t  = blockIdx.x;
    int s0 = g_tok_slot[t*2+0];
    int s1 = g_tok_slot[t*2+1];
    const float4* y0 = (const float4*)(g_Ybuf + (size_t)s0 * D_MOD);
    const float4* y1 = (const float4*)(g_Ybuf + (size_t)s1 * D_MOD);
    float4* o = (float4*)(out + (size_t)t * D_MOD);
    for (int i = threadIdx.x; i < D_MOD/4; i += blockDim.x) {
        float4 a = y0[i], b = y1[i];
        o[i] = make_float4(a.x + b.x, a.y + b.y, a.z + b.z, a.w + b.w);
    }
}

// -------- launch --------
extern "C" void kernel_launch(void* const* d_in, const int* in_sizes, int n_in,
                              void* d_out, int out_size) {
    const float* X  = (const float*)d_in[0];
    const float* Wg = (const float*)d_in[1];
    const float* bg = (const float*)d_in[2];
    const float* W1 = (const float*)d_in[3];
    const float* b1 = (const float*)d_in[4];
    const float* W2 = (const float*)d_in[5];
    const float* b2 = (const float*)d_in[6];
    (void)in_sizes; (void)n_in;

    float* out = (float*)d_out;
    float* out_idx = (out_size >= T_TOK*D_MOD + TOPK*T_TOK) ? out + T_TOK*D_MOD
                                                            : nullptr;

    init_kernel<<<1, 32>>>();
    gate_kernel<<<T_TOK/8, 256>>>(X, Wg, bg, out_idx);
    scatter_kernel<<<1, 1024>>>();

    dim3 g1(H_HID/BN, T_TOK/BM, N_EXP);   // 16 x 16 x 8
    gemm1_kernel<<<g1, 256>>>(W1, b1);
    dim3 g2(D_MOD/BN, T_TOK/BM, N_EXP);   // 8 x 16 x 8
    gemm2_kernel<<<g2, 256>>>(W2, b2);
    combine_kernel<<<T_TOK, 256>>>(out);
}